// round 8
// baseline (speedup 1.0000x reference)
#include <cuda_runtime.h>
#include <cstdint>

#define NB 16
#define NL 1024
#define ND 512
#define NH 256
#define NK 4
#define NROWS (NB * NL)   // 16384

typedef unsigned long long u64;

// ---------------- scratch (static device globals; no allocs) ----------------
__device__ float g_sel [NROWS * NK];     // softmax selections     (256 KB)
__device__ float g_uin [NROWS * NH];     // x @ W_B^T              (16 MB)
__device__ float g_invn[NROWS * NH];     // 1/norm per (row, j)    (16 MB)

// ---------------- helpers ----------------------------------------------------
__device__ __forceinline__ float fast_lg2(float x) {
    float r; asm("lg2.approx.f32 %0, %1;" : "=f"(r) : "f"(x)); return r;
}
__device__ __forceinline__ float fast_ex2(float x) {
    float r; asm("ex2.approx.f32 %0, %1;" : "=f"(r) : "f"(x)); return r;
}
__device__ __forceinline__ uint32_t smem_u32(const void* p) {
    uint32_t a;
    asm("{ .reg .u64 t; cvta.to.shared.u64 t, %1; cvt.u32.u64 %0, t; }"
        : "=r"(a) : "l"(p));
    return a;
}
__device__ __forceinline__ uint32_t mapa_u32(uint32_t a, uint32_t r) {
    uint32_t d;
    asm("mapa.shared::cluster.u32 %0, %1, %2;" : "=r"(d) : "r"(a), "r"(r));
    return d;
}
__device__ __forceinline__ void mbar_wait(uint32_t mb, uint32_t ph) {
    asm volatile(
        "{\n\t.reg .pred p;\n"
        "WL%=:\n\t"
        "mbarrier.try_wait.parity.acquire.cluster.shared::cta.b64 p, [%0], %1;\n\t"
        "@!p bra WL%=;\n\t}"
        :: "r"(mb), "r"(ph) : "memory");
}
// packed f32x2 ops (Blackwell FFMA2 — only reachable via PTX)
__device__ __forceinline__ u64 pk2(float lo, float hi) {
    u64 r; asm("mov.b64 %0, {%1, %2};" : "=l"(r) : "f"(lo), "f"(hi)); return r;
}
__device__ __forceinline__ u64 fma2(u64 a, u64 b, u64 c) {
    u64 d; asm("fma.rn.f32x2 %0, %1, %2, %3;" : "=l"(d) : "l"(a), "l"(b), "l"(c)); return d;
}
__device__ __forceinline__ u64 mul2(u64 a, u64 b) {
    u64 d; asm("mul.rn.f32x2 %0, %1, %2;" : "=l"(d) : "l"(a), "l"(b)); return d;
}
__device__ __forceinline__ float hsum2(u64 v) {
    float lo, hi; asm("mov.b64 {%0, %1}, %2;" : "=f"(lo), "=f"(hi) : "l"(v));
    return lo + hi;
}

// ---------------- kernel 1: selection logits + softmax ----------------------
__global__ __launch_bounds__(256) void sel_kernel(
    const float* __restrict__ x, const float* __restrict__ Wsel,
    const float* __restrict__ bsel)
{
    __shared__ float Ws[NK * ND];
    for (int i = threadIdx.x; i < NK * ND; i += blockDim.x) Ws[i] = Wsel[i];
    __syncthreads();

    int w = threadIdx.x >> 5, l = threadIdx.x & 31;
    int row = blockIdx.x * 8 + w;
    const float* xr = x + row * ND;

    float p0 = 0.f, p1 = 0.f, p2 = 0.f, p3 = 0.f;
    for (int d = l; d < ND; d += 32) {
        float xv = xr[d];
        p0 += xv * Ws[d];
        p1 += xv * Ws[ND + d];
        p2 += xv * Ws[2 * ND + d];
        p3 += xv * Ws[3 * ND + d];
    }
#pragma unroll
    for (int o = 16; o > 0; o >>= 1) {
        p0 += __shfl_xor_sync(0xffffffffu, p0, o);
        p1 += __shfl_xor_sync(0xffffffffu, p1, o);
        p2 += __shfl_xor_sync(0xffffffffu, p2, o);
        p3 += __shfl_xor_sync(0xffffffffu, p3, o);
    }
    if (l == 0) {
        float l0 = p0 + bsel[0], l1 = p1 + bsel[1], l2 = p2 + bsel[2], l3 = p3 + bsel[3];
        float m = fmaxf(fmaxf(l0, l1), fmaxf(l2, l3));
        float e0 = __expf(l0 - m), e1 = __expf(l1 - m), e2 = __expf(l2 - m), e3 = __expf(l3 - m);
        float inv = 1.0f / (e0 + e1 + e2 + e3);
        float4 out = make_float4(e0 * inv, e1 * inv, e2 * inv, e3 * inv);
        *reinterpret_cast<float4*>(&g_sel[row * NK]) = out;
    }
}

// ---------------- kernel 2: FUSED uin (FMA pipe) + norm (MUFU pipe) ---------
// Roles interleaved by blockIdx.x%3 so each SM co-schedules both pipe types.
// blockIdx.x%3 == 2 -> uin role (1024 CTAs); else norm role (2048 CTAs).
__global__ __launch_bounds__(256, 2) void un_kernel(
    const float* __restrict__ X, const float* __restrict__ Wb,
    const float* __restrict__ A)
{
    int bx = blockIdx.x;
    int tid = threadIdx.x;

    if (bx % 3 == 2) {
        // ---------- uin role: u = x @ W_B^T, 64x64 tile ----------
        int uidx = bx / 3;                    // 0..1023
        int n0 = (uidx & 3) * 64;
        int m0 = (uidx >> 2) * 64;

        __shared__ float Xs[16][64];
        __shared__ float Wt[16][64];
        int tx = tid & 15, ty = tid >> 4;
        int lr = tid >> 2, lq = tid & 3;

        float acc[4][4];
#pragma unroll
        for (int r = 0; r < 4; r++)
#pragma unroll
            for (int c2 = 0; c2 < 4; c2++) acc[r][c2] = 0.f;

        for (int k0 = 0; k0 < ND; k0 += 16) {
            float4 xv = *reinterpret_cast<const float4*>(&X [(m0 + lr) * ND + k0 + lq * 4]);
            float4 wv = *reinterpret_cast<const float4*>(&Wb[(n0 + lr) * ND + k0 + lq * 4]);
            __syncthreads();
            Xs[lq * 4 + 0][lr] = xv.x; Xs[lq * 4 + 1][lr] = xv.y;
            Xs[lq * 4 + 2][lr] = xv.z; Xs[lq * 4 + 3][lr] = xv.w;
            Wt[lq * 4 + 0][lr] = wv.x; Wt[lq * 4 + 1][lr] = wv.y;
            Wt[lq * 4 + 2][lr] = wv.z; Wt[lq * 4 + 3][lr] = wv.w;
            __syncthreads();
#pragma unroll
            for (int kk = 0; kk < 16; kk++) {
                float4 a = *reinterpret_cast<const float4*>(&Xs[kk][ty * 4]);
                float4 b = *reinterpret_cast<const float4*>(&Wt[kk][tx * 4]);
                acc[0][0] += a.x * b.x; acc[0][1] += a.x * b.y; acc[0][2] += a.x * b.z; acc[0][3] += a.x * b.w;
                acc[1][0] += a.y * b.x; acc[1][1] += a.y * b.y; acc[1][2] += a.y * b.z; acc[1][3] += a.y * b.w;
                acc[2][0] += a.z * b.x; acc[2][1] += a.z * b.y; acc[2][2] += a.z * b.z; acc[2][3] += a.z * b.w;
                acc[3][0] += a.w * b.x; acc[3][1] += a.w * b.y; acc[3][2] += a.w * b.z; acc[3][3] += a.w * b.w;
            }
        }
#pragma unroll
        for (int r = 0; r < 4; r++) {
            float4 o = make_float4(acc[r][0], acc[r][1], acc[r][2], acc[r][3]);
            *reinterpret_cast<float4*>(&g_uin[(m0 + ty * 4 + r) * NH + n0 + tx * 4]) = o;
        }
    } else {
        // ---------- norm role: inv_norm pre-pass, register-resident A -------
        int nidx = (bx / 3) * 2 + (bx % 3);   // 0..2047
        int jbase = (nidx & 31) * 8;
        int row0 = (nidx >> 5) * (NROWS / 64);    // 256 rows per CTA

        int w = tid >> 5, l = tid & 31;
        int j = jbase + w;

        float4 Ar[8];
#pragma unroll
        for (int r = 0; r < 8; r++)
            Ar[r] = reinterpret_cast<const float4*>(A)[(l + 32 * r) * NH + j];

        const float ninv = -1.0f / 1.2f;
        for (int row = row0; row < row0 + (NROWS / 64); row += 2) {
            float4 sA = __ldg(reinterpret_cast<const float4*>(&g_sel[row * NK]));
            float4 sB = __ldg(reinterpret_cast<const float4*>(&g_sel[(row + 1) * NK]));
            float accA = 0.f, accB = 0.f;
#pragma unroll
            for (int r = 0; r < 8; r++) {
                float a = fmaf(sA.x, Ar[r].x, fmaf(sA.y, Ar[r].y,
                          fmaf(sA.z, Ar[r].z, sA.w * Ar[r].w)));
                float b = fmaf(sB.x, Ar[r].x, fmaf(sB.y, Ar[r].y,
                          fmaf(sB.z, Ar[r].z, sB.w * Ar[r].w)));
                accA += fast_ex2(0.6f * fast_lg2(a * a));
                accB += fast_ex2(0.6f * fast_lg2(b * b));
            }
#pragma unroll
            for (int o = 16; o > 0; o >>= 1) {
                accA += __shfl_xor_sync(0xffffffffu, accA, o);
                accB += __shfl_xor_sync(0xffffffffu, accB, o);
            }
            if (l == 0) {
                g_invn[row * NH + j]       = fast_ex2(fast_lg2(accA) * ninv);
                g_invn[(row + 1) * NH + j] = fast_ex2(fast_lg2(accB) * ninv);
            }
        }
    }
}

// ---------------- kernel 4: scan, 2 batches/cluster, packed f32x2 -----------
// Same protocol as R7 (st.async + tx mbarriers, warp0 tail). The mix
// recompute and matvec now run on FFMA2 (f32x2): adjacent-j pairs packed into
// b64 regs, halving FMA-pipe issue count (the R7 bottleneck at issue=56%).
__global__ __launch_bounds__(512, 1) __cluster_dims__(8, 1, 1)
void scan_kernel(const float* __restrict__ A, float* __restrict__ out)
{
    __shared__ __align__(8) float y_sm[2][32];
    __shared__ float pbuf[2][2][8][32];                 // [parity][batch][src][row]
    __shared__ __align__(8) u64 mbar[2][2];             // [parity][batch]

    int tid = threadIdx.x;
    uint32_t rank;
    asm("mov.u32 %0, %%cluster_ctarank;" : "=r"(rank));
    int c = blockIdx.x >> 3;                 // cluster id -> batches 2c, 2c+1
    int jbase = (int)rank * 32;
    int i = tid >> 1, half = tid & 1;

    // load A pairs (j = jbase + half*16 + 2p, 2p+1) packed per k-component
    u64 Ax[8], Ay[8], Az[8], Aw[8];
#pragma unroll
    for (int p = 0; p < 8; p++) {
        float4 a0 = reinterpret_cast<const float4*>(A)[i * NH + jbase + half * 16 + 2 * p];
        float4 a1 = reinterpret_cast<const float4*>(A)[i * NH + jbase + half * 16 + 2 * p + 1];
        Ax[p] = pk2(a0.x, a1.x); Ay[p] = pk2(a0.y, a1.y);
        Az[p] = pk2(a0.z, a1.z); Aw[p] = pk2(a0.w, a1.w);
    }

    uint32_t mbar_s = smem_u32(mbar);
    if (tid == 0) {
#pragma unroll
        for (int m = 0; m < 4; m++)
            asm volatile("mbarrier.init.shared.b64 [%0], 1;"
                         :: "r"(mbar_s + m * 8) : "memory");
    }
    __syncthreads();
    if (tid == 0) {
#pragma unroll
        for (int m = 0; m < 4; m++)
            asm volatile("mbarrier.arrive.expect_tx.shared.b64 _, [%0], 1024;"
                         :: "r"(mbar_s + m * 8) : "memory");
    }
    __syncthreads();
    asm volatile("barrier.cluster.arrive.aligned;" ::: "memory");
    asm volatile("barrier.cluster.wait.aligned;"  ::: "memory");

    uint32_t dst = (uint32_t)(i >> 5);
    uint32_t lbase = smem_u32(pbuf) + (rank * 32u + (uint32_t)(i & 31)) * 4u;
    uint32_t raddr = mapa_u32(lbase, dst);   // parity stride 2048B, batch stride 1024B
    uint32_t rmbar = mapa_u32(mbar_s, dst);  // parity stride 16B,   batch stride 8B

    const int row0base = (2 * c) * NL;
    const int row1base = (2 * c + 1) * NL;

    float4 s0 = __ldg(reinterpret_cast<const float4*>(&g_sel[row0base * NK]));
    float4 s1 = __ldg(reinterpret_cast<const float4*>(&g_sel[row1base * NK]));
    float inv0 = 0.f, u0 = 0.f, h0 = 0.f;
    float inv1 = 0.f, u1 = 0.f, h1 = 0.f;
    if (tid < 32) {
        inv0 = __ldg(&g_invn[row0base * NH + jbase + tid]);
        u0   = __ldg(&g_uin [row0base * NH + jbase + tid]);
        inv1 = __ldg(&g_invn[row1base * NH + jbase + tid]);
        u1   = __ldg(&g_uin [row1base * NH + jbase + tid]);
    }

    u64 amix0[8], amix1[8];
    {
        u64 sx = pk2(s0.x, s0.x), sy = pk2(s0.y, s0.y),
            sz = pk2(s0.z, s0.z), sw = pk2(s0.w, s0.w);
#pragma unroll
        for (int p = 0; p < 8; p++)
            amix0[p] = fma2(sx, Ax[p], fma2(sy, Ay[p], fma2(sz, Az[p], mul2(sw, Aw[p]))));
        sx = pk2(s1.x, s1.x); sy = pk2(s1.y, s1.y);
        sz = pk2(s1.z, s1.z); sw = pk2(s1.w, s1.w);
#pragma unroll
        for (int p = 0; p < 8; p++)
            amix1[p] = fma2(sx, Ax[p], fma2(sy, Ay[p], fma2(sz, Az[p], mul2(sw, Aw[p]))));
    }

    const u64* y0v = reinterpret_cast<const u64*>(&y_sm[0][half * 16]);
    const u64* y1v = reinterpret_cast<const u64*>(&y_sm[1][half * 16]);

    for (int t = 0; t < NL; t++) {
        const int row0 = row0base + t;
        const int row1 = row1base + t;
        if (tid < 32) {
            y_sm[0][tid] = h0 * inv0;
            y_sm[1][tid] = h1 * inv1;
        }
        __syncthreads();

        const int d = (t < NL - 1) ? 1 : 0;
        float4 s_n0 = __ldg(reinterpret_cast<const float4*>(&g_sel[(row0 + d) * NK]));
        float4 s_n1 = __ldg(reinterpret_cast<const float4*>(&g_sel[(row1 + d) * NK]));
        float inv_n0 = 0.f, u_n0 = 0.f, inv_n1 = 0.f, u_n1 = 0.f;
        if (tid < 32) {
            inv_n0 = __ldg(&g_invn[(row0 + d) * NH + jbase + tid]);
            u_n0   = __ldg(&g_uin [(row0 + d) * NH + jbase + tid]);
            inv_n1 = __ldg(&g_invn[(row1 + d) * NH + jbase + tid]);
            u_n1   = __ldg(&g_uin [(row1 + d) * NH + jbase + tid]);
        }

        const uint32_t poff = (uint32_t)(t & 1);

        // ---- batch 0: packed matvec + store ----
        {
            u64 a0 = mul2(amix0[0], y0v[0]);
            u64 a1 = mul2(amix0[1], y0v[1]);
#pragma unroll
            for (int p = 2; p < 8; p += 2) {
                a0 = fma2(amix0[p],     y0v[p],     a0);
                a1 = fma2(amix0[p + 1], y0v[p + 1], a1);
            }
            float acc = hsum2(a0) + hsum2(a1);
            acc += __shfl_xor_sync(0xffffffffu, acc, 1);
            if (half == 0) {
                asm volatile(
                    "st.async.shared::cluster.mbarrier::complete_tx::bytes.b32 [%0], %1, [%2];"
                    :: "r"(raddr + poff * 2048u), "r"(__float_as_uint(acc)),
                       "r"(rmbar + poff * 16u) : "memory");
            }
        }
        // ---- batch 1: packed matvec + store ----
        {
            u64 a0 = mul2(amix1[0], y1v[0]);
            u64 a1 = mul2(amix1[1], y1v[1]);
#pragma unroll
            for (int p = 2; p < 8; p += 2) {
                a0 = fma2(amix1[p],     y1v[p],     a0);
                a1 = fma2(amix1[p + 1], y1v[p + 1], a1);
            }
            float acc = hsum2(a0) + hsum2(a1);
            acc += __shfl_xor_sync(0xffffffffu, acc, 1);
            if (half == 0) {
                asm volatile(
                    "st.async.shared::cluster.mbarrier::complete_tx::bytes.b32 [%0], %1, [%2];"
                    :: "r"(raddr + poff * 2048u + 1024u), "r"(__float_as_uint(acc)),
                       "r"(rmbar + poff * 16u + 8u) : "memory");
            }
        }

        // hide DSMEM flight: packed amix for t+1, both batches
        {
            u64 sx = pk2(s_n0.x, s_n0.x), sy = pk2(s_n0.y, s_n0.y),
                sz = pk2(s_n0.z, s_n0.z), sw = pk2(s_n0.w, s_n0.w);
#pragma unroll
            for (int p = 0; p < 8; p++)
                amix0[p] = fma2(sx, Ax[p], fma2(sy, Ay[p], fma2(sz, Az[p], mul2(sw, Aw[p]))));
            sx = pk2(s_n1.x, s_n1.x); sy = pk2(s_n1.y, s_n1.y);
            sz = pk2(s_n1.z, s_n1.z); sw = pk2(s_n1.w, s_n1.w);
#pragma unroll
            for (int p = 0; p < 8; p++)
                amix1[p] = fma2(sx, Ax[p], fma2(sy, Ay[p], fma2(sz, Az[p], mul2(sw, Aw[p]))));
        }

        if (tid < 32) {
            const uint32_t ph = (uint32_t)((t >> 1) & 1);
            // ---- batch 0 tail ----
            mbar_wait(mbar_s + poff * 16u, ph);
            if (tid == 0 && t + 2 < NL)
                asm volatile("mbarrier.arrive.expect_tx.shared.b64 _, [%0], 1024;"
                             :: "r"(mbar_s + poff * 16u) : "memory");
            {
                const float* pb = &pbuf[poff][0][0][tid];
                float b0 = pb[0]   + pb[32];
                float b1 = pb[64]  + pb[96];
                float b2 = pb[128] + pb[160];
                float b3 = pb[192] + pb[224];
                float hv = u0 + ((b0 + b1) + (b2 + b3));
                out[row0 * NH + jbase + tid] = hv;
                h0 = hv; inv0 = inv_n0; u0 = u_n0;
            }
            // ---- batch 1 tail ----
            mbar_wait(mbar_s + poff * 16u + 8u, ph);
            if (tid == 0 && t + 2 < NL)
                asm volatile("mbarrier.arrive.expect_tx.shared.b64 _, [%0], 1024;"
                             :: "r"(mbar_s + poff * 16u + 8u) : "memory");
            {
                const float* pb = &pbuf[poff][1][0][tid];
                float b0 = pb[0]   + pb[32];
                float b1 = pb[64]  + pb[96];
                float b2 = pb[128] + pb[160];
                float b3 = pb[192] + pb[224];
                float hv = u1 + ((b0 + b1) + (b2 + b3));
                out[row1 * NH + jbase + tid] = hv;
                h1 = hv; inv1 = inv_n1; u1 = u_n1;
            }
        }
    }

    asm volatile("barrier.cluster.arrive.aligned;" ::: "memory");
    asm volatile("barrier.cluster.wait.aligned;"  ::: "memory");
}

// ---------------- launch ----------------------------------------------------
extern "C" void kernel_launch(void* const* d_in, const int* in_sizes, int n_in,
                              void* d_out, int out_size)
{
    const float* x     = (const float*)d_in[0];   // (16,1024,512)
    const float* Wsel  = (const float*)d_in[1];   // (4,512)
    const float* bsel  = (const float*)d_in[2];   // (4,)
    const float* Wb    = (const float*)d_in[3];   // (256,512)
    const float* Adict = (const float*)d_in[4];   // (256,256,4)
    float* out = (float*)d_out;                   // (16,1024,256)

    sel_kernel<<<NROWS / 8, 256>>>(x, Wsel, bsel);
    un_kernel<<<3072, 256>>>(x, Wb, Adict);       // fused uin + norm
    scan_kernel<<<(NB / 2) * 8, 512>>>(Adict, out);
}